// round 11
// baseline (speedup 1.0000x reference)
#include <cuda_runtime.h>

// Chamfer distance, B=2, N=8192. Symmetric: each pair computed once, feeds both
// row-min (per-gt) and col-min (per-pred). w = c_i + c_j - q.p, c = 0.5||.||^2.
// Queries packed {qA,qB} per f32x2; refs BROADCAST from shared (half-replicated
// {x,x,y,y} layout) -> 1-wavefront LDS. Col-min via per-step warp shfl reduce.

#define BATCH   2
#define NPTS    8192
#define THREADS 128
#define QPT     8                    // queries per thread
#define NGRP    (QPT / 2)            // 4 packed query groups
#define IBLK    (THREADS * QPT)      // 1024 gt rows per CTA
#define ITILES  (NPTS / IBLK)        // 8
#define JSPLITS 55
#define TOTP    (NPTS / 2)           // 4096 pred pairs per batch
#define MAXP    75                   // ceil(4096/55)
#define NCTA    (BATCH * ITILES * JSPLITS)   // 880 <= 888 @6/SM -> one wave

__device__ float    g_rowpart[BATCH * JSPLITS * NPTS];   // 3.6 MB
__device__ float    g_colpart[BATCH * ITILES  * NPTS];   // 0.5 MB
__device__ float    g_blocksum[128];
__device__ unsigned g_done;          // zero-init; self-resets each call

typedef unsigned long long u64;

__device__ __forceinline__ u64 pack2(float lo, float hi) {
    u64 d; asm("mov.b64 %0, {%1,%2};" : "=l"(d) : "f"(lo), "f"(hi)); return d;
}
__device__ __forceinline__ void unpack2(u64 d, float& lo, float& hi) {
    asm("mov.b64 {%0,%1}, %2;" : "=f"(lo), "=f"(hi) : "l"(d));
}
__device__ __forceinline__ u64 fma2(u64 a, u64 b, u64 c) {
    u64 d; asm("fma.rn.f32x2 %0, %1, %2, %3;" : "=l"(d) : "l"(a), "l"(b), "l"(c));
    return d;
}
__device__ __forceinline__ u64 add2(u64 a, u64 b) {
    u64 d; asm("add.rn.f32x2 %0, %1, %2;" : "=l"(d) : "l"(a), "l"(b));
    return d;
}

__global__ __launch_bounds__(THREADS, 6)
void chamfer_pass(const float* __restrict__ pred, const float* __restrict__ gt) {
    const int bid = blockIdx.x;
    const int b   = bid / (ITILES * JSPLITS);
    const int r   = bid - b * (ITILES * JSPLITS);
    const int it  = r / JSPLITS;
    const int js  = r - it * JSPLITS;
    const int ibase  = it * IBLK;
    const int pstart = (js * TOTP) / JSPLITS;
    const int pend   = ((js + 1) * TOTP) / JSPLITS;
    const int npairs = pend - pstart;           // 74 or 75
    const int tid = threadIdx.x;

    // Half-replicated ref layout (read broadcast -> conflict-free by definition):
    // 4*jp+0: {x0,x0,y0,y0}  4*jp+1: {z0,z0,c0,c0}
    // 4*jp+2: {x1,x1,y1,y1}  4*jp+3: {z1,z1,c1,c1}
    __shared__ float4 sref[4 * MAXP];
    __shared__ float2 scm[4][MAXP];   // per-warp col-min {p0,p1}, written once

    if (tid < npairs) {
        const float* p = pred + ((size_t)b * NPTS + 2 * (pstart + tid)) * 3;
        float x0 = p[0], y0 = p[1], z0 = p[2];
        float x1 = p[3], y1 = p[4], z1 = p[5];
        float c0 = 0.5f * (x0 * x0 + y0 * y0 + z0 * z0);
        float c1 = 0.5f * (x1 * x1 + y1 * y1 + z1 * z1);
        sref[4 * tid + 0] = make_float4(x0, x0, y0, y0);
        sref[4 * tid + 1] = make_float4(z0, z0, c0, c0);
        sref[4 * tid + 2] = make_float4(x1, x1, y1, y1);
        sref[4 * tid + 3] = make_float4(z1, z1, c1, c1);
    }

    // Queries (gt): two different queries per u64 half (A = 2g, B = 2g+1), negated.
    u64 qx2[NGRP], qy2[NGRP], qz2[NGRP], qc2[NGRP];
    float rm[QPT];
#pragma unroll
    for (int g = 0; g < NGRP; g++) {
        const float* qa = gt + ((size_t)b * NPTS + ibase + tid + (2 * g) * THREADS) * 3;
        const float* qb = gt + ((size_t)b * NPTS + ibase + tid + (2 * g + 1) * THREADS) * 3;
        float xa = qa[0], ya = qa[1], za = qa[2];
        float xb = qb[0], yb = qb[1], zb = qb[2];
        qx2[g] = pack2(-xa, -xb);
        qy2[g] = pack2(-ya, -yb);
        qz2[g] = pack2(-za, -zb);
        qc2[g] = pack2(0.5f * (xa * xa + ya * ya + za * za),
                       0.5f * (xb * xb + yb * yb + zb * zb));
        rm[2 * g]     = 3.4e38f;
        rm[2 * g + 1] = 3.4e38f;
    }
    __syncthreads();

    const int w    = tid >> 5;
    const int lane = tid & 31;
    const ulonglong2* __restrict__ pref = reinterpret_cast<const ulonglong2*>(sref);
    float2* __restrict__ cmrow = scm[w];

#pragma unroll 2
    for (int jp = 0; jp < npairs; jp++) {
        ulonglong2 v0 = pref[4 * jp];       // {x0,x0},{y0,y0}   (broadcast)
        ulonglong2 w0 = pref[4 * jp + 1];   // {z0,z0},{c0,c0}
        ulonglong2 v1 = pref[4 * jp + 2];   // {x1,x1},{y1,y1}
        ulonglong2 w1 = pref[4 * jp + 3];   // {z1,z1},{c1,c1}
        float cp0 = 3.4e38f, cp1 = 3.4e38f;
#pragma unroll
        for (int g = 0; g < NGRP; g++) {
            u64 h0 = fma2(qz2[g], w0.x, add2(qc2[g], w0.y));
            h0 = fma2(qy2[g], v0.y, h0);
            h0 = fma2(qx2[g], v0.x, h0);
            float a, bq; unpack2(h0, a, bq);       // {w(A,p0), w(B,p0)}
            rm[2 * g]     = fminf(rm[2 * g],     a);
            rm[2 * g + 1] = fminf(rm[2 * g + 1], bq);
            cp0 = fminf(cp0, fminf(a, bq));

            u64 h1 = fma2(qz2[g], w1.x, add2(qc2[g], w1.y));
            h1 = fma2(qy2[g], v1.y, h1);
            h1 = fma2(qx2[g], v1.x, h1);
            float cq, dq; unpack2(h1, cq, dq);     // {w(A,p1), w(B,p1)}
            rm[2 * g]     = fminf(rm[2 * g],     cq);
            rm[2 * g + 1] = fminf(rm[2 * g + 1], dq);
            cp1 = fminf(cp1, fminf(cq, dq));
        }
        // Warp min over this warp's 256 queries for refs (p0, p1).
#pragma unroll
        for (int o = 16; o; o >>= 1) {
            cp0 = fminf(cp0, __shfl_xor_sync(0xffffffffu, cp0, o));
            cp1 = fminf(cp1, __shfl_xor_sync(0xffffffffu, cp1, o));
        }
        if (lane == 0) cmrow[jp] = make_float2(cp0, cp1);
    }
    __syncthreads();

    // Row-min partials, coalesced.
    float* rout = g_rowpart + ((size_t)(b * JSPLITS + js)) * NPTS + ibase;
#pragma unroll
    for (int k = 0; k < QPT; k++)
        rout[tid + k * THREADS] = rm[k];

    // Col-min partials: combine 4 warp rows, float2 per pair.
    if (tid < npairs) {
        float2 m = scm[0][tid];
#pragma unroll
        for (int u = 1; u < 4; u++) {
            float2 v = scm[u][tid];
            m.x = fminf(m.x, v.x);
            m.y = fminf(m.y, v.y);
        }
        float2* cout = reinterpret_cast<float2*>(
            g_colpart + ((size_t)(b * ITILES + it)) * NPTS + 2 * (pstart + tid));
        cout[0] = m;
    }
}

// Reduce: 128 blocks. Per-block: min over splits, sqrt, block sum. The LAST
// block to finish (fence + counter) sums the 128 block sums in fixed tree
// order (deterministic) and writes the result; counter self-resets.
__global__ __launch_bounds__(256)
void chamfer_reduce(float* __restrict__ out) {
    __shared__ float ssum[256];
    __shared__ int s_last;
    const int qid = blockIdx.x * 256 + threadIdx.x;   // 0..32767
    float mv = 3.4e38f;
    if (qid < BATCH * NPTS) {
        const int b = qid >> 13, i = qid & (NPTS - 1);
        const float* p = g_rowpart + (size_t)b * JSPLITS * NPTS + i;
#pragma unroll 5
        for (int t = 0; t < JSPLITS; t++) mv = fminf(mv, p[(size_t)t * NPTS]);
    } else {
        const int q = qid - BATCH * NPTS;
        const int b = q >> 13, j = q & (NPTS - 1);
        const float* p = g_colpart + (size_t)b * ITILES * NPTS + j;
#pragma unroll
        for (int t = 0; t < ITILES; t++) mv = fminf(mv, p[(size_t)t * NPTS]);
    }
    ssum[threadIdx.x] = sqrtf(fmaxf(2.0f * mv, 0.0f));
    __syncthreads();
    for (int s = 128; s > 0; s >>= 1) {
        if (threadIdx.x < s) ssum[threadIdx.x] += ssum[threadIdx.x + s];
        __syncthreads();
    }
    if (threadIdx.x == 0) {
        g_blocksum[blockIdx.x] = ssum[0];
        __threadfence();
        unsigned t = atomicAdd(&g_done, 1u);
        s_last = (t == 127u);
    }
    __syncthreads();
    if (s_last) {
        volatile float* bs = g_blocksum;
        if (threadIdx.x < 128) ssum[threadIdx.x] = bs[threadIdx.x];
        __syncthreads();
        for (int s = 64; s > 0; s >>= 1) {
            if (threadIdx.x < s) ssum[threadIdx.x] += ssum[threadIdx.x + s];
            __syncthreads();
        }
        if (threadIdx.x == 0) {
            out[0] = ssum[0] / (float)(BATCH * NPTS);
            g_done = 0;   // reset for next graph replay
        }
    }
}

extern "C" void kernel_launch(void* const* d_in, const int* in_sizes, int n_in,
                              void* d_out, int out_size) {
    const float* pred = (const float*)d_in[0];
    const float* gt   = (const float*)d_in[1];
    float* out        = (float*)d_out;

    chamfer_pass<<<NCTA, THREADS>>>(pred, gt);
    chamfer_reduce<<<128, 256>>>(out);
}

// round 12
// speedup vs baseline: 1.2192x; 1.2192x over previous
#include <cuda_runtime.h>

// Chamfer distance, B=2, N=8192. Symmetric: each pair computed once, feeds both
// row-min (per-gt) and col-min (per-pred). w = c_i + c_j - q.p, c = 0.5||.||^2.
// Dual-order f32x2 (R10 inner loop), THREADS=256 for steady 6 warps/SMSP,
// fused full-unroll reduce with done-counter final sum (2 launches).

#define BATCH   2
#define NPTS    8192
#define THREADS 256
#define QPT     8                    // queries per thread
#define NGRP    (QPT / 2)            // 4 packed query groups
#define IBLK    (THREADS * QPT)      // 2048 gt rows per CTA
#define ITILES  (NPTS / IBLK)        // 4
#define JSPLITS 55
#define TOTP    (NPTS / 2)           // 4096 pred pairs per batch
#define MAXP    75                   // ceil(4096/55)
#define NCTA    (BATCH * ITILES * JSPLITS)   // 440 <= 444 @3/SM -> one wave
#define RBLOCKS 256

__device__ float    g_rowpart[BATCH * JSPLITS * NPTS];   // 3.6 MB
__device__ float    g_colpart[BATCH * ITILES  * NPTS];   // 0.25 MB
__device__ float    g_blocksum[RBLOCKS];
__device__ unsigned g_done;          // zero-init; self-resets each call

typedef unsigned long long u64;

__device__ __forceinline__ u64 pack2(float lo, float hi) {
    u64 d; asm("mov.b64 %0, {%1,%2};" : "=l"(d) : "f"(lo), "f"(hi)); return d;
}
__device__ __forceinline__ void unpack2(u64 d, float& lo, float& hi) {
    asm("mov.b64 {%0,%1}, %2;" : "=f"(lo), "=f"(hi) : "l"(d));
}
__device__ __forceinline__ u64 fma2(u64 a, u64 b, u64 c) {
    u64 d; asm("fma.rn.f32x2 %0, %1, %2, %3;" : "=l"(d) : "l"(a), "l"(b), "l"(c));
    return d;
}
__device__ __forceinline__ u64 add2(u64 a, u64 b) {
    u64 d; asm("add.rn.f32x2 %0, %1, %2;" : "=l"(d) : "l"(a), "l"(b));
    return d;
}

__global__ __launch_bounds__(THREADS, 3)
void chamfer_pass(const float* __restrict__ pred, const float* __restrict__ gt) {
    const int bid = blockIdx.x;
    const int b   = bid / (ITILES * JSPLITS);
    const int r   = bid - b * (ITILES * JSPLITS);
    const int it  = r / JSPLITS;
    const int js  = r - it * JSPLITS;
    const int ibase  = it * IBLK;
    const int pstart = (js * TOTP) / JSPLITS;
    const int pend   = ((js + 1) * TOTP) / JSPLITS;
    const int npairs = pend - pstart;           // 74 or 75 (>= 32 for lane-skew)
    const int tid = threadIdx.x;

    // 16B-stride arrays (conflict-free under lane-consecutive jp):
    __shared__ float4 sXY1[MAXP];   // {x0,x1,y0,y1}
    __shared__ float4 sZC1[MAXP];   // {z0,z1,c0,c1}
    __shared__ float4 sXY2[MAXP];   // {x1,x0,y1,y0}
    __shared__ float4 sZC2[MAXP];   // {z1,z0,c1,c0}
    __shared__ float2 scm[THREADS / 32][MAXP]; // per-warp col-min {p0,p1}

    if (tid < npairs) {
        const float* p = pred + ((size_t)b * NPTS + 2 * (pstart + tid)) * 3;
        float x0 = p[0], y0 = p[1], z0 = p[2];
        float x1 = p[3], y1 = p[4], z1 = p[5];
        float c0 = 0.5f * (x0 * x0 + y0 * y0 + z0 * z0);
        float c1 = 0.5f * (x1 * x1 + y1 * y1 + z1 * z1);
        sXY1[tid] = make_float4(x0, x1, y0, y1);
        sZC1[tid] = make_float4(z0, z1, c0, c1);
        sXY2[tid] = make_float4(x1, x0, y1, y0);
        sZC2[tid] = make_float4(z1, z0, c1, c0);
    }
    if (tid < MAXP) {
#pragma unroll
        for (int u = 0; u < THREADS / 32; u++)
            scm[u][tid] = make_float2(3.4e38f, 3.4e38f);
    }

    // Queries (gt): two different queries per u64 (A = slot 2g, B = slot 2g+1).
    u64 qx2[NGRP], qy2[NGRP], qz2[NGRP], qc2[NGRP];
    float rm[QPT];
#pragma unroll
    for (int g = 0; g < NGRP; g++) {
        const float* qa = gt + ((size_t)b * NPTS + ibase + tid + (2 * g) * THREADS) * 3;
        const float* qb = gt + ((size_t)b * NPTS + ibase + tid + (2 * g + 1) * THREADS) * 3;
        float xa = qa[0], ya = qa[1], za = qa[2];
        float xb = qb[0], yb = qb[1], zb = qb[2];
        qx2[g] = pack2(-xa, -xb);
        qy2[g] = pack2(-ya, -yb);
        qz2[g] = pack2(-za, -zb);
        qc2[g] = pack2(0.5f * (xa * xa + ya * ya + za * za),
                       0.5f * (xb * xb + yb * yb + zb * zb));
        rm[2 * g]     = 3.4e38f;
        rm[2 * g + 1] = 3.4e38f;
    }
    __syncthreads();

    const int w    = tid >> 5;
    const int lane = tid & 31;
    const ulonglong2* __restrict__ pXY1 = reinterpret_cast<const ulonglong2*>(sXY1);
    const ulonglong2* __restrict__ pZC1 = reinterpret_cast<const ulonglong2*>(sZC1);
    const ulonglong2* __restrict__ pXY2 = reinterpret_cast<const ulonglong2*>(sXY2);
    const ulonglong2* __restrict__ pZC2 = reinterpret_cast<const ulonglong2*>(sZC2);
    float2* __restrict__ cmrow = scm[w];

    // Lane-skewed pair walk: at each step lanes hold distinct jp (npairs >= 32)
    // -> race-free col-min RMW in the warp's private row.
    int jp = lane;
#pragma unroll 2
    for (int s = 0; s < npairs; s++) {
        ulonglong2 vxy1 = pXY1[jp];     // {x0,x1},{y0,y1}
        ulonglong2 vzc1 = pZC1[jp];     // {z0,z1},{c0,c1}
        ulonglong2 vxy2 = pXY2[jp];     // {x1,x0},{y1,y0}
        ulonglong2 vzc2 = pZC2[jp];     // {z1,z0},{c1,c0}
        float2 cm = cmrow[jp];
        float cp0 = cm.x, cp1 = cm.y;
#pragma unroll
        for (int g = 0; g < NGRP; g++) {
            u64 h1 = fma2(qz2[g], vzc1.x, add2(qc2[g], vzc1.y));
            h1 = fma2(qy2[g], vxy1.y, h1);
            h1 = fma2(qx2[g], vxy1.x, h1);
            u64 h2 = fma2(qz2[g], vzc2.x, add2(qc2[g], vzc2.y));
            h2 = fma2(qy2[g], vxy2.y, h2);
            h2 = fma2(qx2[g], vxy2.x, h2);
            float a0, b1; unpack2(h1, a0, b1);   // w(A,p0), w(B,p1)
            float a1, b0; unpack2(h2, a1, b0);   // w(A,p1), w(B,p0)
            rm[2 * g]     = fminf(rm[2 * g],     fminf(a0, a1));
            rm[2 * g + 1] = fminf(rm[2 * g + 1], fminf(b0, b1));
            cp0 = fminf(cp0, fminf(a0, b0));
            cp1 = fminf(cp1, fminf(a1, b1));
        }
        cmrow[jp] = make_float2(cp0, cp1);
        jp++; if (jp == npairs) jp = 0;
    }
    __syncthreads();

    // Row-min partials, coalesced.
    float* rout = g_rowpart + ((size_t)(b * JSPLITS + js)) * NPTS + ibase;
#pragma unroll
    for (int k = 0; k < QPT; k++)
        rout[tid + k * THREADS] = rm[k];

    // Col-min partials: combine warp rows, float2 per pair.
    if (tid < npairs) {
        float2 m = scm[0][tid];
#pragma unroll
        for (int u = 1; u < THREADS / 32; u++) {
            float2 v = scm[u][tid];
            m.x = fminf(m.x, v.x);
            m.y = fminf(m.y, v.y);
        }
        float2* cout = reinterpret_cast<float2*>(
            g_colpart + ((size_t)(b * ITILES + it)) * NPTS + 2 * (pstart + tid));
        cout[0] = m;
    }
}

// Fused reduce: 256 blocks x 128 threads, one thread per query slot.
// FULL unroll -> front-batched loads (high MLP). Last block (fence + counter)
// sums the 256 block sums in fixed order; counter self-resets.
__global__ __launch_bounds__(128)
void chamfer_reduce(float* __restrict__ out) {
    __shared__ float ssum[128];
    __shared__ int s_last;
    const int qid = blockIdx.x * 128 + threadIdx.x;   // 0..32767
    float mv = 3.4e38f;
    if (qid < BATCH * NPTS) {
        const int b = qid >> 13, i = qid & (NPTS - 1);
        const float* p = g_rowpart + (size_t)b * JSPLITS * NPTS + i;
#pragma unroll
        for (int t = 0; t < JSPLITS; t++) mv = fminf(mv, p[(size_t)t * NPTS]);
    } else {
        const int q = qid - BATCH * NPTS;
        const int b = q >> 13, j = q & (NPTS - 1);
        const float* p = g_colpart + (size_t)b * ITILES * NPTS + j;
#pragma unroll
        for (int t = 0; t < ITILES; t++) mv = fminf(mv, p[(size_t)t * NPTS]);
    }
    ssum[threadIdx.x] = sqrtf(fmaxf(2.0f * mv, 0.0f));
    __syncthreads();
    for (int s = 64; s > 0; s >>= 1) {
        if (threadIdx.x < s) ssum[threadIdx.x] += ssum[threadIdx.x + s];
        __syncthreads();
    }
    if (threadIdx.x == 0) {
        g_blocksum[blockIdx.x] = ssum[0];
        __threadfence();
        unsigned t = atomicAdd(&g_done, 1u);
        s_last = (t == RBLOCKS - 1u);
    }
    __syncthreads();
    if (s_last) {
        volatile float* bs = g_blocksum;
        float acc = bs[threadIdx.x] + bs[threadIdx.x + 128];
        ssum[threadIdx.x] = acc;
        __syncthreads();
        for (int s = 64; s > 0; s >>= 1) {
            if (threadIdx.x < s) ssum[threadIdx.x] += ssum[threadIdx.x + s];
            __syncthreads();
        }
        if (threadIdx.x == 0) {
            out[0] = ssum[0] / (float)(BATCH * NPTS);
            g_done = 0;   // reset for next graph replay
        }
    }
}

extern "C" void kernel_launch(void* const* d_in, const int* in_sizes, int n_in,
                              void* d_out, int out_size) {
    const float* pred = (const float*)d_in[0];
    const float* gt   = (const float*)d_in[1];
    float* out        = (float*)d_out;

    chamfer_pass<<<NCTA, THREADS>>>(pred, gt);
    chamfer_reduce<<<RBLOCKS, 128>>>(out);
}